// round 6
// baseline (speedup 1.0000x reference)
#include <cuda_runtime.h>
#include <cuda_bf16.h>
#include <math.h>

// pred/target: (32, 3, 512, 512) fp32 -> scalar fp32 mean |sobel(gray(p)) - sobel(gray(t))|
#define B      32
#define H      512
#define W      512
#define PLANE  (H * W)
#define IMG    (3 * PLANE)
#define NPIX   (B * PLANE)            // 8388608

#define RT     16                     // rows per CTA tile (fine-grained for load balance)
#define TILESY (H / RT)               // 32
#define NBLK   (B * TILESY)           // 1024
#define TPB    256
#define SROW   520                    // smem row stride (floats); data at [4..515], zeros at 3/516

__device__ float        g_partials[NBLK];
__device__ unsigned int g_count = 0;

__device__ __forceinline__ float fsqrt_approx(float x) {
    float r; asm("sqrt.approx.f32 %0, %1;" : "=f"(r) : "f"(x)); return r;
}

// 3-channel float4 load for one row quad (zero-filled outside image).
__device__ __forceinline__ void ldg3(const float* __restrict__ img, int gy, int q,
                                     float4& r, float4& g, float4& bl)
{
    if ((unsigned)gy < (unsigned)H) {
        const float* p = img + (size_t)gy * W + 4 * q;
        r  = *(const float4*)p;
        g  = *(const float4*)(p + PLANE);
        bl = *(const float4*)(p + 2 * PLANE);
    } else {
        r = g = bl = make_float4(0.f, 0.f, 0.f, 0.f);
    }
}

__device__ __forceinline__ float4 gray4(float4 r, float4 g, float4 bl)
{
    float4 v;
    v.x = 0.299f * r.x + 0.587f * g.x + 0.114f * bl.x;
    v.y = 0.299f * r.y + 0.587f * g.y + 0.114f * bl.y;
    v.z = 0.299f * r.z + 0.587f * g.z + 0.114f * bl.z;
    v.w = 0.299f * r.w + 0.587f * g.w + 0.114f * bl.w;
    return v;
}

// Horizontal separable partials at column c from a staged gray row.
__device__ __forceinline__ void rdrow(const float* __restrict__ base, int c,
                                      float& hx, float& hs)
{
    float l  = base[3 + c];
    float m  = base[4 + c];
    float rr = base[5 + c];
    hx = rr - l;                 // [-1, 0, 1]
    hs = l + 2.f * m + rr;       // [ 1, 2, 1]
}

__global__ __launch_bounds__(TPB, 4) void edge_loss_fused(
    const float* __restrict__ pred, const float* __restrict__ tgt,
    float* __restrict__ out)
{
    // Ring: [img 0/1][slot 0/1][SROW]  (8.3 KB)
    __shared__ float ring[4 * SROW];

    const int tile = blockIdx.x;
    const int b    = blockIdx.y;
    const int gy0  = tile * RT;
    const int tid  = threadIdx.x;

    // Staging role: thread stages quad q of image im.
    const int q  = tid & 127;
    const int im = tid >> 7;
    const float* simg = (im ? tgt : pred) + (size_t)b * IMG;

    // x-halo zeros (never overwritten; STS writes only [4..515]).
    if (tid < 4) { ring[tid * SROW + 3] = 0.f; ring[tid * SROW + 516] = 0.f; }

    // ---- Prologue: stage rows k=-1 (slot 1) and k=0 (slot 0) ----
    {
        float4 r, g, bl;
        ldg3(simg, gy0 - 1, q, r, g, bl);
        *(float4*)(ring + ((im << 1) | 1) * SROW + 4 + 4 * q) = gray4(r, g, bl);
        ldg3(simg, gy0, q, r, g, bl);
        *(float4*)(ring + ((im << 1) | 0) * SROW + 4 + 4 * q) = gray4(r, g, bl);
    }
    // Prefetch row k=1 into registers.
    float4 fr, fg, fb;
    ldg3(simg, gy0 + 1, q, fr, fg, fb);
    __syncthreads();

    // ---- Build rolling windows for rows -1 and 0.
    //      Combos j: img = j>>1, col = (j&1) ? tid+256 : tid ----
    const int c0 = tid, c1 = tid + 256;
    float hx0[4], hx1[4], hs0[4], hs1[4];
    #pragma unroll
    for (int j = 0; j < 4; j++) {
        const int ib = (j >> 1) << 1;
        const int c  = (j & 1) ? c1 : c0;
        rdrow(ring + (ib | 1) * SROW, c, hx0[j], hs0[j]);   // row -1 (slot 1)
        rdrow(ring + (ib | 0) * SROW, c, hx1[j], hs1[j]);   // row  0 (slot 0)
    }
    __syncthreads();   // all reads of slot 1 done before iter 0 overwrites it

    // ---- Pipelined mainloop: STS(r+1) -> LDG(r+2) -> bar -> compute(r) ----
    float acc = 0.f;
    #pragma unroll 2
    for (int r = 0; r < RT; r++) {
        const int s = (r + 1) & 1;
        *(float4*)(ring + ((im << 1) | s) * SROW + 4 + 4 * q) = gray4(fr, fg, fb);
        if (r < RT - 1)
            ldg3(simg, gy0 + r + 2, q, fr, fg, fb);
        __syncthreads();

        float mag[4];
        #pragma unroll
        for (int j = 0; j < 4; j++) {
            const float* bnew = ring + ((((j >> 1) << 1)) | s) * SROW;
            const int c = (j & 1) ? c1 : c0;
            float hx2, hs2;
            rdrow(bnew, c, hx2, hs2);
            float ex = hx0[j] + 2.f * hx1[j] + hx2;
            float ey = hs2 - hs0[j];
            mag[j] = fsqrt_approx(ex * ex + ey * ey);
            hx0[j] = hx1[j]; hx1[j] = hx2;
            hs0[j] = hs1[j]; hs1[j] = hs2;
        }
        acc += fabsf(mag[0] - mag[2]) + fabsf(mag[1] - mag[3]);
    }

    // ---- Block reduction (fixed order) ----
    #pragma unroll
    for (int off = 16; off > 0; off >>= 1)
        acc += __shfl_down_sync(0xffffffffu, acc, off);

    __shared__ float wsum[8];
    __shared__ bool  isLast;
    const int lane = tid & 31, wid = tid >> 5;
    if (lane == 0) wsum[wid] = acc;
    __syncthreads();
    if (tid < 8) {
        float v = wsum[tid];
        #pragma unroll
        for (int off = 4; off > 0; off >>= 1)
            v += __shfl_down_sync(0x000000ffu, v, off);
        if (tid == 0) {
            g_partials[b * TILESY + tile] = v;
            __threadfence();
            unsigned int old = atomicAdd(&g_count, 1u);
            isLast = (old == (unsigned)(NBLK - 1));
        }
    }
    __syncthreads();

    // ---- Fused deterministic final reduction (last block, fp64 fixed order) ----
    if (isLast) {
        __shared__ double ds[TPB];
        double a = 0.0;
        #pragma unroll
        for (int i = 0; i < NBLK / TPB; i++)
            a += (double)__ldcg(&g_partials[tid + i * TPB]);
        ds[tid] = a;
        __syncthreads();
        #pragma unroll
        for (int st = TPB / 2; st > 0; st >>= 1) {
            if (tid < st) ds[tid] += ds[tid + st];
            __syncthreads();
        }
        if (tid == 0) {
            out[0] = (float)(ds[0] / (double)NPIX);
            g_count = 0;   // self-reset for graph replay
        }
    }
}

extern "C" void kernel_launch(void* const* d_in, const int* in_sizes, int n_in,
                              void* d_out, int out_size)
{
    const float* pred = (const float*)d_in[0];
    const float* tgt  = (const float*)d_in[1];
    float* out = (float*)d_out;

    dim3 grid(TILESY, B);   // (32, 32) = 1024 blocks — fine-grained for SM load balance
    edge_loss_fused<<<grid, TPB>>>(pred, tgt, out);
}